// round 2
// baseline (speedup 1.0000x reference)
#include <cuda_runtime.h>

#define W 224
#define H 224
#define BC 192
#define STEPS 32
#define BANDS 8
#define ROWS_PER_BAND (H / BANDS)     // 28
#define IMG_PIX (H * W)
#define TPB 256                        // 8 warps, each covers 31 useful columns
#define GRID (BC * BANDS)              // 1536

// Global scratch (zero-initialized at module load; the finalizing block
// re-zeroes everything it consumed, so every kernel_launch call starts clean).
__device__ int g_hist[BC * STEPS];
__device__ unsigned int g_count;

// searchsorted(linspace(0,1,32), f, 'left') for f in [0,1):
// first j with t_j >= f, t_j = fl(j * fl(1/31)) (j<31), t_31 = 1.0.
// ceil(31f) is off by at most 1; two exact-grid fixups make it bit-exact.
__device__ __forceinline__ int binof(float f) {
    const float step = 1.0f / 31.0f;
    int g = __float2int_ru(f * 31.0f);
    if (g > 0 && (float)(g - 1) * step >= f) g--;
    if (g < 31 && (float)g * step < f) g++;
    return g;
}

__global__ __launch_bounds__(TPB) void ecc_fused(const float* __restrict__ x,
                                                 float* __restrict__ out) {
    // Per-thread private histogram columns: hist[bin][thread].
    // 256 % 32 == 0 => bank(hist[j][t]) = t % 32 => conflict-free always.
    __shared__ int hist[STEPS][TPB];
    __shared__ bool s_last;

    const int tid  = threadIdx.x;
    const int wid  = tid >> 5;
    const int lane = tid & 31;
    const int col  = wid * 31 + lane;          // overlapped-warp column map
    const int bc   = blockIdx.x >> 3;
    const int band = blockIdx.x & 7;
    const int r0   = band * ROWS_PER_BAND;

    const bool own  = (lane < 31) && (col < W);        // this lane owns vertex `col`
    const bool hasR = own && (col < W - 1);            // h-edge / square exist

    const int colc = (col < W) ? col : (W - 1);        // clamped load column
    const float* __restrict__ p = x + (long)bc * IMG_PIX + r0 * W + colc;

#pragma unroll
    for (int j = 0; j < STEPS; j++) hist[j][tid] = 0;
    __syncthreads();

    // Row r0 bins; right-neighbor via shfl (valid for lanes 0..30 = all owners).
    int b  = binof(__ldg(p));
    int br = __shfl_down_sync(0xffffffffu, b, 1);

    const int nIter = (band == BANDS - 1) ? (ROWS_PER_BAND - 1) : ROWS_PER_BAND;

#pragma unroll 4
    for (int it = 0; it < nIter; it++) {
        p += W;
        const int nb  = binof(__ldg(p));                       // row h+1
        const int nbr = __shfl_down_sync(0xffffffffu, nb, 1);

        // Cells at pixel (h, col):  +v(b)  -he(e1)  -ve(e2)  +sq(q)
        const int e1 = max(b, br);
        const int e2 = max(b, nb);
        const int q  = max(e1, max(nb, nbr));
        if (own) {
            const bool p1 = hasR && (e1 != b);   // vertex/h-edge survive pairing
            if (!hasR || p1) hist[b][tid]  += 1;
            if (p1)          hist[e1][tid] -= 1;
            const bool p2 = hasR && (q != e2);   // v-edge/square survive pairing
            if (!hasR || p2) hist[e2][tid] -= 1;
            if (p2)          hist[q][tid]  += 1;
        }
        b = nb; br = nbr;
    }

    // Tail: row 223 (last band only) — vertex + h-edge, no v-edge/square.
    if (band == BANDS - 1 && own) {
        const int e1 = max(b, br);
        const bool p1 = hasR && (e1 != b);
        if (!hasR || p1) hist[b][tid]  += 1;
        if (p1)          hist[e1][tid] -= 1;
    }
    __syncthreads();

    // Block reduction: warp w owns bins {w, w+8, w+16, w+24}.
    for (int j = wid; j < STEPS; j += (TPB / 32)) {
        int sum = 0;
#pragma unroll
        for (int t = lane; t < TPB; t += 32) sum += hist[j][t];
#pragma unroll
        for (int o = 16; o; o >>= 1) sum += __shfl_down_sync(0xffffffffu, sum, o);
        if (lane == 0) atomicAdd(&g_hist[bc * STEPS + j], sum);
    }

    // Last-block-done: the final block computes the cumsum and resets scratch.
    __threadfence();
    __syncthreads();
    if (tid == 0)
        s_last = (atomicAdd(&g_count, 1u) == (unsigned)(GRID - 1));
    __syncthreads();

    if (s_last) {
        __threadfence();  // acquire: make all blocks' g_hist atomics visible
        // 8 warps scan 192 groups of 32 bins (inclusive scan per group).
        for (int g = wid; g < BC; g += (TPB / 32)) {
            int v = __ldcg(&g_hist[g * STEPS + lane]);
#pragma unroll
            for (int o = 1; o < 32; o <<= 1) {
                int t = __shfl_up_sync(0xffffffffu, v, o);
                if (lane >= o) v += t;
            }
            out[g * STEPS + lane] = (float)v;
            g_hist[g * STEPS + lane] = 0;        // clean for next replay
        }
        if (tid == 0) g_count = 0u;
    }
}

extern "C" void kernel_launch(void* const* d_in, const int* in_sizes, int n_in,
                              void* d_out, int out_size) {
    const float* x = (const float*)d_in[0];
    float* out = (float*)d_out;
    (void)in_sizes; (void)n_in; (void)out_size;
    ecc_fused<<<GRID, TPB>>>(x, out);
}

// round 4
// speedup vs baseline: 1.1651x; 1.1651x over previous
#include <cuda_runtime.h>

#define W 224
#define H 224
#define BC 192
#define STEPS 32
#define BANDS 8
#define ROWS_PER_BAND 28
#define IMG_PIX (H * W)
#define TPB 256
#define NWARP 8
#define GRID (BC * BANDS)

// Global scratch (zero-initialized at load; last block re-zeroes for replays).
// NOTE: with the alive-mask formulation, g_hist[bc][j] accumulates the
// *cumulative* Euler characteristic at t_j directly — no final cumsum.
__device__ int g_hist[BC * STEPS];
__device__ unsigned int g_count;

// searchsorted(linspace(0,1,32), f, 'left') for f in [0,1). Bit-exact vs ref.
__device__ __forceinline__ int binof(float f) {
    const float step = 1.0f / 31.0f;
    int g = __float2int_ru(f * 31.0f);
    if (g > 0 && (float)(g - 1) * step >= f) g--;
    if (g < 31 && (float)g * step < f) g++;
    return g;
}

// Add a 1-bit-per-bin mask into 5 bit-sliced counter planes (count <= 31).
__device__ __forceinline__ void csa5(unsigned c[5], unsigned x) {
    unsigned t;
    t = c[0] & x; c[0] ^= x; x = t;
    t = c[1] & x; c[1] ^= x; x = t;
    t = c[2] & x; c[2] ^= x; x = t;
    t = c[3] & x; c[3] ^= x; x = t;
    c[4] ^= x;
}

// Warp 32x32 bit-matrix transpose: out lane j bit k = in lane k bit j.
__device__ __forceinline__ unsigned tr32(unsigned v, int lane) {
    unsigned w;
    w = __shfl_xor_sync(0xffffffffu, v, 16);
    v = (lane & 16) ? ((v & 0xFFFF0000u) | ((w >> 16) & 0x0000FFFFu))
                    : ((v & 0x0000FFFFu) | ((w << 16) & 0xFFFF0000u));
    w = __shfl_xor_sync(0xffffffffu, v, 8);
    v = (lane & 8)  ? ((v & 0xFF00FF00u) | ((w >> 8)  & 0x00FF00FFu))
                    : ((v & 0x00FF00FFu) | ((w << 8)  & 0xFF00FF00u));
    w = __shfl_xor_sync(0xffffffffu, v, 4);
    v = (lane & 4)  ? ((v & 0xF0F0F0F0u) | ((w >> 4)  & 0x0F0F0F0Fu))
                    : ((v & 0x0F0F0F0Fu) | ((w << 4)  & 0xF0F0F0F0u));
    w = __shfl_xor_sync(0xffffffffu, v, 2);
    v = (lane & 2)  ? ((v & 0xCCCCCCCCu) | ((w >> 2)  & 0x33333333u))
                    : ((v & 0x33333333u) | ((w << 2)  & 0xCCCCCCCCu));
    w = __shfl_xor_sync(0xffffffffu, v, 1);
    v = (lane & 1)  ? ((v & 0xAAAAAAAAu) | ((w >> 1)  & 0x55555555u))
                    : ((v & 0x55555555u) | ((w << 1)  & 0xAAAAAAAAu));
    return v;
}

struct RowState {
    const float* p;
    unsigned m, mr;
};

// Process pixel row h (mask m, right-nbr mr); load row h+1.
// Interior col: net alive per bin = P - N with P=[b,e1), N=[e2,q).
// Edge col (no right nbr): vertex + v-edge only: P = m & ~mn.
__device__ __forceinline__ void step_row(RowState& s, unsigned ownM, unsigned hasRM,
                                         bool hasR, unsigned pP[5], unsigned pN[5]) {
    s.p += W;
    const unsigned mn  = 0xFFFFFFFFu << binof(__ldg(s.p));
    const unsigned mnr = __shfl_down_sync(0xffffffffu, mn, 1);
    unsigned P = hasR ? (s.m & ~s.mr) : (s.m & ~mn);
    P &= ownM;
    unsigned N = (s.m & mn) & ~(s.mr & mnr) & hasRM;
    csa5(pP, P);
    csa5(pN, N);
    s.m = mn; s.mr = mnr;
}

__global__ __launch_bounds__(TPB) void ecc_bits(const float* __restrict__ x,
                                                float* __restrict__ out) {
    __shared__ int s_cnt[NWARP][STEPS];
    __shared__ bool s_last;

    const int tid  = threadIdx.x;
    const int wid  = tid >> 5;
    const int lane = tid & 31;
    const int col  = wid * 31 + lane;            // overlapped-warp column map
    const int bc   = blockIdx.x >> 3;
    const int band = blockIdx.x & 7;
    const int r0   = band * ROWS_PER_BAND;

    const bool own  = (lane < 31) && (col < W);
    const bool hasR = own && (col < W - 1);
    const unsigned ownM  = own  ? 0xFFFFFFFFu : 0u;
    const unsigned hasRM = hasR ? 0xFFFFFFFFu : 0u;
    const int colc = (col < W) ? col : (W - 1);

    unsigned pP[5] = {0, 0, 0, 0, 0};
    unsigned pN[5] = {0, 0, 0, 0, 0};

    RowState s;
    s.p  = x + (long)bc * IMG_PIX + r0 * W + colc;
    s.m  = 0xFFFFFFFFu << binof(__ldg(s.p));
    s.mr = __shfl_down_sync(0xffffffffu, s.m, 1);

#pragma unroll 9
    for (int it = 0; it < 27; it++)
        step_row(s, ownM, hasRM, hasR, pP, pN);

    if (band != BANDS - 1) {
        step_row(s, ownM, hasRM, hasR, pP, pN);   // 28th full row
    } else {
        // Row 223: vertex + h-edge only (no row below).
        unsigned P = (hasR ? (s.m & ~s.mr) : s.m) & ownM;
        csa5(pP, P);
    }

    // Warp epilogue: transpose planes, popc -> signed chi-contribution @bin lane.
    int cnt = 0;
#pragma unroll
    for (int i = 0; i < 5; i++) cnt += (int)__popc(tr32(pP[i], lane)) << i;
#pragma unroll
    for (int i = 0; i < 5; i++) cnt -= (int)__popc(tr32(pN[i], lane)) << i;
    s_cnt[wid][lane] = cnt;
    __syncthreads();

    if (wid == 0) {
        int sum = 0;
#pragma unroll
        for (int w2 = 0; w2 < NWARP; w2++) sum += s_cnt[w2][lane];
        atomicAdd(&g_hist[bc * STEPS + lane], sum);
    }

    // Last-block-done: g_hist already holds ECC(t_j) — just cast out + reset.
    __threadfence();
    __syncthreads();
    if (tid == 0)
        s_last = (atomicAdd(&g_count, 1u) == (unsigned)(GRID - 1));
    __syncthreads();

    if (s_last) {
        __threadfence();
        for (int g2 = wid; g2 < BC; g2 += NWARP) {
            const int v = __ldcg(&g_hist[g2 * STEPS + lane]);
            out[g2 * STEPS + lane] = (float)v;
            g_hist[g2 * STEPS + lane] = 0;       // clean for next replay
        }
        if (tid == 0) g_count = 0u;
    }
}

extern "C" void kernel_launch(void* const* d_in, const int* in_sizes, int n_in,
                              void* d_out, int out_size) {
    const float* x = (const float*)d_in[0];
    float* out = (float*)d_out;
    (void)in_sizes; (void)n_in; (void)out_size;
    ecc_bits<<<GRID, TPB>>>(x, out);
}